// round 12
// baseline (speedup 1.0000x reference)
#include <cuda_runtime.h>
#include <cuda_fp16.h>
#include <math.h>

#define BB 16
#define HH 12
#define NN 784
#define NROWS (BB * NN)          // 12544
#define NBLOCKS 296              // 2 per SM x 148; all resident (GB300 has 152 SMs)
#define ROWS_BASE 42
#define EXTRA 112                // first 112 blocks take 43 rows: 296*42+112 = 12544
#define ROWS_MAX 43
#define STAGE_BYTES (HH * NN * 4)          // 37632
#define RETAIN_BYTES (ROWS_MAX * NN * 2)   // 67424
#define DYN_BYTES (STAGE_BYTES + RETAIN_BYTES)  // 105056 -> 2 blocks/SM by smem

__device__ float2 g_rowstats[NROWS];   // (rowmax, rowsumexp)
__device__ float2 g_batch[BB];         // (gmax, 1/sum)
__device__ int    g_c1;                // arrival counter (self-resets)
__device__ int    g_c2;                // departure counter (self-resets)
__device__ int    g_flag;              // combine-done flag (self-resets)

__global__ void __launch_bounds__(384, 2) k_all(const float* __restrict__ m,
                                                float* __restrict__ out) {
    extern __shared__ char dyn[];
    float*  stage  = (float*)dyn;                       // HH x NN staging
    __half* retain = (__half*)(dyn + STAGE_BYTES);      // cnt x NN exp values

    __shared__ float rs[HH], red[HH];
    __shared__ float s_bcast;
    __shared__ float s_rowmax[ROWS_MAX];
    __shared__ float s_scale[ROWS_MAX];
    __shared__ int   s_last;

    const int k    = blockIdx.x;
    const int cnt  = ROWS_BASE + (k < EXTRA ? 1 : 0);
    const int start = k * ROWS_BASE + (k < EXTRA ? k : EXTRA);
    const int t    = threadIdx.x;
    const int w    = t >> 5;
    const int lane = t & 31;

    float4* smrow = (float4*)(stage + w * NN);

    // ---- prologue: prefetch row 'start' into regs ----
    float4 v[7];
    {
        int b0 = start / NN, i0 = start - b0 * NN;
        const float4* row = (const float4*)(m + ((size_t)(b0 * HH + w) * NN + i0) * NN);
        #pragma unroll
        for (int q = 0; q < 6; q++) v[q] = __ldcs(row + lane + 32 * q);
        if (lane < 4) v[6] = __ldcs(row + 192 + lane);
    }

    // ================= phase 1: aggregate + per-row exp into SMEM =========
    for (int r = 0; r < cnt; r++) {
        const int bi = start + r;

        // rowsum from regs, store regs -> staging
        float s = 0.f;
        #pragma unroll
        for (int q = 0; q < 6; q++) {
            s += (v[q].x + v[q].y) + (v[q].z + v[q].w);
            smrow[lane + 32 * q] = v[q];
        }
        if (lane < 4) {
            s += (v[6].x + v[6].y) + (v[6].z + v[6].w);
            smrow[192 + lane] = v[6];
        }
        #pragma unroll
        for (int o = 16; o; o >>= 1) s += __shfl_xor_sync(0xffffffffu, s, o);
        if (lane == 0) rs[w] = s;

        // prefetch next row (overlaps with FMA phase below)
        if (r + 1 < cnt) {
            int nbi = bi + 1;
            int nb = nbi / NN, ni = nbi - nb * NN;
            const float4* nrow = (const float4*)(m + ((size_t)(nb * HH + w) * NN + ni) * NN);
            #pragma unroll
            for (int q = 0; q < 6; q++) v[q] = __ldcs(nrow + lane + 32 * q);
            if (lane < 4) v[6] = __ldcs(nrow + 192 + lane);
        }
        __syncthreads();                                  // (B) staging + rs ready

        float rr[HH];
        #pragma unroll
        for (int h = 0; h < HH; h++) rr[h] = rs[h];

        float a0 = 0.f, a1 = 0.f, a2 = 0.f;
        #pragma unroll
        for (int h = 0; h < HH; h++) {
            a0 = fmaf(stage[h * NN + t],       rr[h], a0);
            a1 = fmaf(stage[h * NN + t + 384], rr[h], a1);
        }
        if (t < 16) {
            #pragma unroll
            for (int h = 0; h < HH; h++) a2 = fmaf(stage[h * NN + t + 768], rr[h], a2);
        }

        float mx = fmaxf(a0, a1);
        if (t < 16) mx = fmaxf(mx, a2);
        #pragma unroll
        for (int o = 16; o; o >>= 1) mx = fmaxf(mx, __shfl_xor_sync(0xffffffffu, mx, o));
        if (lane == 0) red[w] = mx;
        __syncthreads();                                  // (C)
        if (t == 0) {
            float M = red[0];
            #pragma unroll
            for (int h = 1; h < HH; h++) M = fmaxf(M, red[h]);
            s_bcast = M;
        }
        __syncthreads();                                  // (D)
        const float rowmax = s_bcast;
        if (t == 0) s_rowmax[r] = rowmax;

        __half* rrow = retain + (size_t)r * NN;
        float e0 = expf(a0 - rowmax);
        float e1 = expf(a1 - rowmax);
        rrow[t]       = __float2half_rn(e0);
        rrow[t + 384] = __float2half_rn(e1);
        float sume = e0 + e1;
        if (t < 16) {
            float e2 = expf(a2 - rowmax);
            rrow[t + 768] = __float2half_rn(e2);
            sume += e2;
        }
        #pragma unroll
        for (int o = 16; o; o >>= 1) sume += __shfl_xor_sync(0xffffffffu, sume, o);
        if (lane == 0) red[w] = sume;
        __syncthreads();                                  // (E)
        if (t == 0) {
            float S = 0.f;
            #pragma unroll
            for (int h = 0; h < HH; h++) S += red[h];
            g_rowstats[bi] = make_float2(rowmax, S);
        }
    }

    // ================= arrival + combine (last block) =====================
    if (t == 0) {
        __threadfence();                     // publish this block's rowstats
        int c = atomicAdd(&g_c1, 1);
        s_last = (c == NBLOCKS - 1);
    }
    __syncthreads();

    if (s_last) {
        // warp w handles batches w, w+12
        for (int b = w; b < BB; b += HH) {
            const float2* st = g_rowstats + b * NN;
            float gm = -1e30f;
            for (int r2 = lane; r2 < NN; r2 += 32) gm = fmaxf(gm, __ldcg(&st[r2].x));
            #pragma unroll
            for (int o = 16; o; o >>= 1) gm = fmaxf(gm, __shfl_xor_sync(0xffffffffu, gm, o));
            float ss = 0.f;
            for (int r2 = lane; r2 < NN; r2 += 32) {
                float rm = __ldcg(&st[r2].x);
                float rv = __ldcg(&st[r2].y);
                ss += rv * expf(rm - gm);
            }
            #pragma unroll
            for (int o = 16; o; o >>= 1) ss += __shfl_xor_sync(0xffffffffu, ss, o);
            if (lane == 0) g_batch[b] = make_float2(gm, 1.f / ss);
        }
        __syncthreads();
        if (t == 0) {
            g_c1 = 0;                         // reset arrivals (all arrived)
            __threadfence();                  // g_batch visible before flag
            atomicExch(&g_flag, 1);
        }
    }

    // ================= wait for combine =====================
    if (t == 0) {
        while (*(volatile int*)&g_flag == 0) __nanosleep(64);
    }
    __syncthreads();

    // ================= phase 2: scale + write out =====================
    if (t < cnt) {
        int bi = start + t;
        int b = bi / NN;
        float gm  = __ldcg(&g_batch[b].x);
        float inv = __ldcg(&g_batch[b].y);
        s_scale[t] = expf(s_rowmax[t] - gm) * inv;
    }
    __syncthreads();

    float4* op = (float4*)out + (size_t)start * 196;   // 196 float4 per row
    const uint2* rp = (const uint2*)retain;            // 4 halves per uint2
    const int nf = cnt * 196;
    for (int f = t; f < nf; f += 384) {
        int rl = f / 196;
        float sc = s_scale[rl];
        uint2 h = rp[f];
        float2 f0 = __half22float2(*(__half2*)&h.x);
        float2 f1 = __half22float2(*(__half2*)&h.y);
        op[f] = make_float4(f0.x * sc, f0.y * sc, f1.x * sc, f1.y * sc);
    }

    // ================= departure: reset flag =====================
    if (t == 0) {
        int d = atomicAdd(&g_c2, 1);
        if (d == NBLOCKS - 1) { g_c2 = 0; g_flag = 0; }
    }
}

// ---------------------------------------------------------------------------
extern "C" void kernel_launch(void* const* d_in, const int* in_sizes, int n_in,
                              void* d_out, int out_size) {
    const float* m = (const float*)d_in[0];
    float* out = (float*)d_out;

    cudaFuncSetAttribute(k_all, cudaFuncAttributeMaxDynamicSharedMemorySize, DYN_BYTES);
    k_all<<<NBLOCKS, 384, DYN_BYTES>>>(m, out);
}

// round 13
// speedup vs baseline: 1.4860x; 1.4860x over previous
#include <cuda_runtime.h>
#include <cuda_fp16.h>
#include <math.h>

#define BB 16
#define HH 12
#define NN 784
#define NROWS (BB * NN)        // 12544
#define NSQ (NN * NN)          // 614656

// Device-global scratch (allocation is forbidden; __device__ globals are allowed)
__device__ __half g_scratch[(size_t)BB * NSQ];   // exp(x - rowmax), ~19.7 MB
__device__ float2 g_rowstats[NROWS];             // (rowmax, rowsumexp)
__device__ float  g_rowscale[NROWS];             // exp(rowmax - gmax) / sum_b

// ---------------------------------------------------------------------------
// k_agg: R5/R9/R11-proven (79.4us, ~6.05 TB/s — LTS-cap bound). One block per
// (b,i); 12 warps stage the 12 head rows in SMEM (+rowsums); block computes
// agg[l] = sum_h m[h][l]*rowsum[h], row max, exp (fp16 to scratch), row
// expsum, per-row stats. __ldcs on the touch-once input stream keeps the
// L2-resident scratch from being evicted.
// ---------------------------------------------------------------------------
__global__ __launch_bounds__(384) void k_agg(const float* __restrict__ m) {
    __shared__ float sm[HH * NN];   // 37632 B
    __shared__ float rs[HH];
    __shared__ float red[HH];
    __shared__ float s_bcast;

    const int bi = blockIdx.x;          // b*NN + i
    const int b  = bi / NN;
    const int i  = bi - b * NN;
    const int t    = threadIdx.x;
    const int w    = t >> 5;
    const int lane = t & 31;

    const float4* row = (const float4*)(m + ((size_t)(b * HH + w) * NN + i) * NN);
    float4* smrow = (float4*)(sm + w * NN);
    float s = 0.f;
    #pragma unroll
    for (int j = lane; j < NN / 4; j += 32) {
        float4 v = __ldcs(row + j);
        smrow[j] = v;
        s += (v.x + v.y) + (v.z + v.w);
    }
    #pragma unroll
    for (int o = 16; o; o >>= 1) s += __shfl_xor_sync(0xffffffffu, s, o);
    if (lane == 0) rs[w] = s;
    __syncthreads();

    float rr[HH];
    #pragma unroll
    for (int h = 0; h < HH; h++) rr[h] = rs[h];

    float a0 = 0.f, a1 = 0.f, a2 = 0.f;
    #pragma unroll
    for (int h = 0; h < HH; h++) {
        a0 = fmaf(sm[h * NN + t],       rr[h], a0);
        a1 = fmaf(sm[h * NN + t + 384], rr[h], a1);
    }
    if (t < 16) {
        #pragma unroll
        for (int h = 0; h < HH; h++) a2 = fmaf(sm[h * NN + t + 768], rr[h], a2);
    }

    float mx = fmaxf(a0, a1);
    if (t < 16) mx = fmaxf(mx, a2);
    #pragma unroll
    for (int o = 16; o; o >>= 1) mx = fmaxf(mx, __shfl_xor_sync(0xffffffffu, mx, o));
    if (lane == 0) red[w] = mx;
    __syncthreads();
    if (t == 0) {
        float M = red[0];
        #pragma unroll
        for (int h = 1; h < HH; h++) M = fmaxf(M, red[h]);
        s_bcast = M;
    }
    __syncthreads();
    const float rowmax = s_bcast;

    __half* srow = g_scratch + (size_t)bi * NN;
    float e0 = expf(a0 - rowmax);
    float e1 = expf(a1 - rowmax);
    srow[t]       = __float2half_rn(e0);
    srow[t + 384] = __float2half_rn(e1);
    float sume = e0 + e1;
    if (t < 16) {
        float e2 = expf(a2 - rowmax);
        srow[t + 768] = __float2half_rn(e2);
        sume += e2;
    }
    #pragma unroll
    for (int o = 16; o; o >>= 1) sume += __shfl_xor_sync(0xffffffffu, sume, o);
    if (lane == 0) red[w] = sume;
    __syncthreads();
    if (t == 0) {
        float S = 0.f;
        #pragma unroll
        for (int h = 0; h < HH; h++) S += red[h];
        g_rowstats[bi] = make_float2(rowmax, S);
    }
}

// ---------------------------------------------------------------------------
// k_combine: R9-proven. One block per batch, 784 active threads (one row
// each); 2-phase tree reduction -> gmax, 1/sum; per-row scale. Deterministic.
// ---------------------------------------------------------------------------
__global__ __launch_bounds__(800) void k_combine() {
    const int b = blockIdx.x;
    const int t = threadIdx.x;
    __shared__ float red[25];
    __shared__ float s_gmax, s_inv;

    const bool act = (t < NN);
    float2 st = act ? g_rowstats[b * NN + t] : make_float2(-1e30f, 0.f);

    float mx = st.x;
    #pragma unroll
    for (int o = 16; o; o >>= 1) mx = fmaxf(mx, __shfl_xor_sync(0xffffffffu, mx, o));
    if ((t & 31) == 0) red[t >> 5] = mx;
    __syncthreads();
    if (t == 0) {
        float M = red[0];
        #pragma unroll
        for (int k = 1; k < 25; k++) M = fmaxf(M, red[k]);
        s_gmax = M;
    }
    __syncthreads();
    const float gmax = s_gmax;

    float s = act ? st.y * expf(st.x - gmax) : 0.f;
    #pragma unroll
    for (int o = 16; o; o >>= 1) s += __shfl_xor_sync(0xffffffffu, s, o);
    __syncthreads();
    if ((t & 31) == 0) red[t >> 5] = s;
    __syncthreads();
    if (t == 0) {
        float S = 0.f;
        #pragma unroll
        for (int k = 0; k < 25; k++) S += red[k];
        s_inv = 1.f / S;
    }
    __syncthreads();

    if (act) g_rowscale[b * NN + t] = expf(st.x - gmax) * s_inv;
}

// ---------------------------------------------------------------------------
// k_norm: R5/R9/R11-proven local optimum (beat MLP-chains, pair-per-thread
// with and without __stcs, fused-combine, and persistent variants head-to-
// head). One int4 (8 halves) -> 2 float4 per thread, plain stores.
// Total int4 = 1,229,312 = 4802 blocks * 256 exactly.
// ---------------------------------------------------------------------------
__global__ __launch_bounds__(256) void k_norm(float* __restrict__ out) {
    const int j = blockIdx.x * 256 + threadIdx.x;   // int4 index
    const int row = j / 98;                          // 98 int4 per row (784/8)
    const float sc = g_rowscale[row];

    int4 v = ((const int4*)g_scratch)[j];
    float2 f0 = __half22float2(*(__half2*)&v.x);
    float2 f1 = __half22float2(*(__half2*)&v.y);
    float2 f2 = __half22float2(*(__half2*)&v.z);
    float2 f3 = __half22float2(*(__half2*)&v.w);

    float4 o0 = make_float4(f0.x * sc, f0.y * sc, f1.x * sc, f1.y * sc);
    float4 o1 = make_float4(f2.x * sc, f2.y * sc, f3.x * sc, f3.y * sc);
    ((float4*)out)[2 * j]     = o0;
    ((float4*)out)[2 * j + 1] = o1;
}

// ---------------------------------------------------------------------------
extern "C" void kernel_launch(void* const* d_in, const int* in_sizes, int n_in,
                              void* d_out, int out_size) {
    const float* m = (const float*)d_in[0];
    float* out = (float*)d_out;

    k_agg<<<NROWS, 384>>>(m);
    k_combine<<<BB, 800>>>();
    k_norm<<<4802, 256>>>(out);
}